// round 5
// baseline (speedup 1.0000x reference)
#include <cuda_runtime.h>

#define FWSZ 524288u
#define QKS  262144u
typedef unsigned long long ull;

static __device__ __forceinline__ ull pack2(float lo, float hi){
  ull r; asm("mov.b64 %0,{%1,%2};" : "=l"(r) : "f"(lo), "f"(hi)); return r;
}
static __device__ __forceinline__ void fma2(ull &d, ull a, ull b){
  asm("fma.rn.f32x2 %0,%1,%2,%0;" : "+l"(d) : "l"(a), "l"(b));
}
static __device__ __forceinline__ float2 unpack2(ull v){
  float2 f; asm("mov.b64 {%0,%1},%2;" : "=f"(f.x), "=f"(f.y) : "l"(v)); return f;
}

// plane offsets: NX 0..7, Q 8..15, K 16..23, V 24..31, A 32..39, H 40..63, NH 64..87, T 88..119
__device__ float g_scratch[120u*FWSZ + 65536u];

// ---------------- plain float4 copy ----------------
__global__ void k_copy(const float* __restrict__ s, float* __restrict__ d){
  unsigned i = blockIdx.x*256u + threadIdx.x;
  ((float4*)d)[i] = ((const float4*)s)[i];
}

// ---------------- layernorm over F axis, per (c,w); affine g[c,f],b[c,f] ----------------
__global__ __launch_bounds__(256) void k_ln(const float* __restrict__ in, const float* __restrict__ g,
                                            const float* __restrict__ b, float* __restrict__ o){
  int c = blockIdx.y, lane = threadIdx.x & 31, fg = threadIdx.x >> 5;
  int w = blockIdx.x*32 + lane;
  const float* base = in + (size_t)c*FWSZ + w;
  float s = 0.f, s2 = 0.f;
  for (int f = fg; f < 1024; f += 8){ float v = base[(size_t)f*512u]; s += v; s2 += v*v; }
  __shared__ float sh[2][8][32];
  sh[0][fg][lane] = s; sh[1][fg][lane] = s2;
  __syncthreads();
  float S = 0.f, S2 = 0.f;
  #pragma unroll
  for (int r = 0; r < 8; r++){ S += sh[0][r][lane]; S2 += sh[1][r][lane]; }
  float mu  = S*(1.f/1024.f);
  float var = S2*(1.f/1024.f) - mu*mu;
  float rs  = rsqrtf(var + 1e-8f);
  float* ob = o + (size_t)c*FWSZ + w;
  const float* gb = g + c*1024; const float* bb = b + c*1024;
  for (int f = fg; f < 1024; f += 8)
    ob[(size_t)f*512u] = (base[(size_t)f*512u]-mu)*rs*gb[f] + bb[f];
}

// ---------------- 1x3 conv, pad W=1; OCP packed output-channel pairs; 2 pixels/thread ----------------
template<int IC, int OCP>
__global__ __launch_bounds__(256) void k_conv1x3(const float* __restrict__ in, const float* __restrict__ wgt,
                                                 float* __restrict__ o){
  __shared__ ull ws[OCP*IC*3];
  for (int i = threadIdx.x; i < OCP*IC*3; i += 256){
    int p = i/(IC*3), r = i - p*IC*3;
    ws[i] = pack2(wgt[(2*p)*IC*3 + r], wgt[(2*p+1)*IC*3 + r]);
  }
  __syncthreads();
  unsigned t = blockIdx.x*256u + threadIdx.x;
  unsigned base = t*2u;            // even pixel pair
  int w = base & 511u;
  ull acc[OCP][2];
  #pragma unroll
  for (int p = 0; p < OCP; p++){ acc[p][0] = 0ull; acc[p][1] = 0ull; }
  #pragma unroll
  for (int ic = 0; ic < IC; ic++){
    const float* ip = in + (size_t)ic*FWSZ + base;
    float v0 = (w > 0)   ? ip[-1] : 0.f;
    float v1 = ip[0];
    float v2 = ip[1];
    float v3 = (w < 510) ? ip[2] : 0.f;
    ull b0 = pack2(v0,v0), b1 = pack2(v1,v1), b2 = pack2(v2,v2), b3 = pack2(v3,v3);
    #pragma unroll
    for (int p = 0; p < OCP; p++){
      const ull* wp = &ws[(p*IC+ic)*3];
      ull w0 = wp[0], w1 = wp[1], w2 = wp[2];
      fma2(acc[p][0], b0, w0); fma2(acc[p][0], b1, w1); fma2(acc[p][0], b2, w2);
      fma2(acc[p][1], b1, w0); fma2(acc[p][1], b2, w1); fma2(acc[p][1], b3, w2);
    }
  }
  #pragma unroll
  for (int p = 0; p < OCP; p++){
    float2 a = unpack2(acc[p][0]), bvv = unpack2(acc[p][1]);
    o[(size_t)(2*p)*FWSZ   + base]     = a.x;
    o[(size_t)(2*p+1)*FWSZ + base]     = a.y;
    o[(size_t)(2*p)*FWSZ   + base + 1] = bvv.x;
    o[(size_t)(2*p+1)*FWSZ + base + 1] = bvv.y;
  }
}

// ---------------- QK^T GEMM: out[qw][kw] = scale*sum_dd Q[dd][qw]K[dd][kw] + b1 + b2 (+ b3) ----------------
// Q,K planes: [z][dd 0..127][w 0..511]; out at z*QKS. grid (4,4,64), block 256.
__global__ __launch_bounds__(256) void k_gemm_qk(const float* __restrict__ Q, const float* __restrict__ K,
    const float* __restrict__ b1p, const float* __restrict__ b2p, const float* __restrict__ b3p,
    float* __restrict__ o){
  int z = blockIdx.z, qw0 = blockIdx.y*128, kw0 = blockIdx.x*128;
  const float* Qb = Q + (size_t)z*65536u + qw0;
  const float* Kb = K + (size_t)z*65536u + kw0;
  __shared__ __align__(16) float As[16][128], Bs[16][128];
  int tid = threadIdx.x, tx = tid & 15, ty = tid >> 4;
  ull acc[8][4];
  #pragma unroll
  for (int i = 0; i < 8; i++)
    #pragma unroll
    for (int j = 0; j < 4; j++) acc[i][j] = 0ull;
  for (int d0 = 0; d0 < 128; d0 += 16){
    #pragma unroll
    for (int r = 0; r < 2; r++){
      int idx = tid + 256*r;
      int kk = idx >> 5, m4 = (idx & 31)*4;
      *(float4*)&As[kk][m4] = *(const float4*)&Qb[(size_t)(d0+kk)*512u + m4];
      *(float4*)&Bs[kk][m4] = *(const float4*)&Kb[(size_t)(d0+kk)*512u + m4];
    }
    __syncthreads();
    #pragma unroll
    for (int kk = 0; kk < 16; kk++){
      float4 a0 = *(float4*)&As[kk][ty*8], a1 = *(float4*)&As[kk][ty*8+4];
      float4 p0 = *(float4*)&Bs[kk][tx*8], p1 = *(float4*)&Bs[kk][tx*8+4];
      ull pb0 = pack2(p0.x,p0.y), pb1 = pack2(p0.z,p0.w), pb2 = pack2(p1.x,p1.y), pb3 = pack2(p1.z,p1.w);
      float aa[8] = {a0.x,a0.y,a0.z,a0.w,a1.x,a1.y,a1.z,a1.w};
      #pragma unroll
      for (int i = 0; i < 8; i++){
        ull ab = pack2(aa[i], aa[i]);
        fma2(acc[i][0], ab, pb0); fma2(acc[i][1], ab, pb1);
        fma2(acc[i][2], ab, pb2); fma2(acc[i][3], ab, pb3);
      }
    }
    __syncthreads();
  }
  const float sc = 0.08838834764831845f;  // 1/sqrt(128)
  #pragma unroll
  for (int i = 0; i < 8; i++){
    size_t rb = (size_t)z*QKS + (size_t)(qw0 + ty*8 + i)*512u + kw0 + tx*8;
    #pragma unroll
    for (int j = 0; j < 4; j++){
      float2 v = unpack2(acc[i][j]);
      size_t ix = rb + j*2;
      float2 c1 = *(const float2*)(b1p + ix), c2 = *(const float2*)(b2p + ix);
      float o0 = v.x*sc + c1.x + c2.x, o1 = v.y*sc + c1.y + c2.y;
      if (b3p){ float2 c3 = *(const float2*)(b3p + ix); o0 += c3.x; o1 += c3.y; }
      *(float2*)(o + ix) = make_float2(o0, o1);
    }
  }
}

// ---------------- softmax row stats: rowmax + 1/sum(exp) over 512-wide rows ----------------
__global__ __launch_bounds__(128) void k_stats(const float* __restrict__ pq, float* __restrict__ mx,
                                               float* __restrict__ inv){
  size_t row = blockIdx.x;
  int t = threadIdx.x;
  float4 v = ((const float4*)(pq + row*512u))[t];
  float m = fmaxf(fmaxf(v.x, v.y), fmaxf(v.z, v.w));
  #pragma unroll
  for (int o = 16; o; o >>= 1) m = fmaxf(m, __shfl_xor_sync(0xffffffffu, m, o));
  __shared__ float sm[4], ss[4];
  if ((t & 31) == 0) sm[t >> 5] = m;
  __syncthreads();
  m = fmaxf(fmaxf(sm[0], sm[1]), fmaxf(sm[2], sm[3]));
  float s = expf(v.x-m) + expf(v.y-m) + expf(v.z-m) + expf(v.w-m);
  #pragma unroll
  for (int o = 16; o; o >>= 1) s += __shfl_xor_sync(0xffffffffu, s, o);
  if ((t & 31) == 0) ss[t >> 5] = s;
  __syncthreads();
  if (t == 0){ mx[row] = m; inv[row] = 1.f/(ss[0]+ss[1]+ss[2]+ss[3]); }
}

// ---------------- AV GEMM with fused softmax: A[dd][qw] = inv[qw]*sum_kw exp(pq[qw][kw]-mx[qw])*V[dd][kw] ----------------
// grid (4,1,64): 4 qw-tiles x 64 (c,h). block 256.
__global__ __launch_bounds__(256) void k_gemm_av(const float* __restrict__ V, const float* __restrict__ pq,
    const float* __restrict__ mx, const float* __restrict__ inv, float* __restrict__ A){
  int z = blockIdx.z, qw0 = blockIdx.x*128;
  const float* Vb  = V  + (size_t)z*65536u;
  const float* Pb  = pq + (size_t)z*QKS;
  const float* mxb = mx + z*512 + qw0;
  __shared__ __align__(16) float As[16][132], Bs[16][132];   // [kk][dd], [kk][qw]
  int tid = threadIdx.x, tx = tid & 15, ty = tid >> 4;
  ull acc[8][4];
  #pragma unroll
  for (int i = 0; i < 8; i++)
    #pragma unroll
    for (int j = 0; j < 4; j++) acc[i][j] = 0ull;
  for (int kw0 = 0; kw0 < 512; kw0 += 16){
    #pragma unroll
    for (int r = 0; r < 8; r++){
      int idx = tid + 256*r;          // 0..2047
      int m = idx >> 4, kk = idx & 15;
      As[kk][m] = Vb[(size_t)m*512u + kw0 + kk];
      Bs[kk][m] = expf(Pb[(size_t)(qw0 + m)*512u + kw0 + kk] - mxb[m]);
    }
    __syncthreads();
    #pragma unroll
    for (int kk = 0; kk < 16; kk++){
      float4 a0 = *(float4*)&As[kk][ty*8], a1 = *(float4*)&As[kk][ty*8+4];
      float4 p0 = *(float4*)&Bs[kk][tx*8], p1 = *(float4*)&Bs[kk][tx*8+4];
      ull pb0 = pack2(p0.x,p0.y), pb1 = pack2(p0.z,p0.w), pb2 = pack2(p1.x,p1.y), pb3 = pack2(p1.z,p1.w);
      float aa[8] = {a0.x,a0.y,a0.z,a0.w,a1.x,a1.y,a1.z,a1.w};
      #pragma unroll
      for (int i = 0; i < 8; i++){
        ull ab = pack2(aa[i], aa[i]);
        fma2(acc[i][0], ab, pb0); fma2(acc[i][1], ab, pb1);
        fma2(acc[i][2], ab, pb2); fma2(acc[i][3], ab, pb3);
      }
    }
    __syncthreads();
  }
  #pragma unroll
  for (int i = 0; i < 8; i++){
    size_t rb = ((size_t)z*128u + ty*8 + i)*512u + qw0 + tx*8;
    #pragma unroll
    for (int j = 0; j < 4; j++){
      float2 v  = unpack2(acc[i][j]);
      float2 iv = *(const float2*)(inv + z*512 + qw0 + tx*8 + j*2);
      *(float2*)(A + rb + j*2) = make_float2(v.x*iv.x, v.y*iv.y);
    }
  }
}

// ---------------- 3x3 conv, pad (1,1); OCP packed oc pairs; 2 pixels/thread; optional sqrelu / +x ----------------
template<int IC, int OCP, bool SQRELU>
__global__ __launch_bounds__(256) void k_conv3x3(const float* __restrict__ in, const float* __restrict__ wgt,
    const float* __restrict__ addsrc, float* __restrict__ o){
  __shared__ ull ws[OCP*IC*9];
  for (int i = threadIdx.x; i < OCP*IC*9; i += 256){
    int p = i/(IC*9), r = i - p*IC*9;
    ws[i] = pack2(wgt[(2*p)*IC*9 + r], wgt[(2*p+1)*IC*9 + r]);
  }
  __syncthreads();
  unsigned t = blockIdx.x*256u + threadIdx.x;
  unsigned base = t*2u;
  int w = base & 511u, f = base >> 9;
  ull acc[OCP][2];
  #pragma unroll
  for (int p = 0; p < OCP; p++){ acc[p][0] = 0ull; acc[p][1] = 0ull; }
  #pragma unroll
  for (int ic = 0; ic < IC; ic++){
    const float* ip = in + (size_t)ic*FWSZ + base;
    float u[3][4];
    #pragma unroll
    for (int dy = 0; dy < 3; dy++){
      bool rv = (dy == 1) || (dy == 0 ? (f > 0) : (f < 1023));
      const float* rp = ip + (dy-1)*512;
      u[dy][0] = (rv && w > 0)   ? rp[-1] : 0.f;
      u[dy][1] = rv ? rp[0] : 0.f;
      u[dy][2] = rv ? rp[1] : 0.f;
      u[dy][3] = (rv && w < 510) ? rp[2] : 0.f;
    }
    #pragma unroll
    for (int k = 0; k < 9; k++){
      int ky = k/3, kx = k - ky*3;
      ull b0 = pack2(u[ky][kx],   u[ky][kx]);
      ull b1 = pack2(u[ky][kx+1], u[ky][kx+1]);
      #pragma unroll
      for (int p = 0; p < OCP; p++){
        ull wv = ws[(p*IC+ic)*9 + k];
        fma2(acc[p][0], b0, wv); fma2(acc[p][1], b1, wv);
      }
    }
  }
  #pragma unroll
  for (int p = 0; p < OCP; p++){
    float2 a = unpack2(acc[p][0]), bv = unpack2(acc[p][1]);
    float o00 = a.x, o10 = a.y, o01 = bv.x, o11 = bv.y;
    if (SQRELU){
      o00 = fmaxf(o00,0.f); o00 *= o00;  o10 = fmaxf(o10,0.f); o10 *= o10;
      o01 = fmaxf(o01,0.f); o01 *= o01;  o11 = fmaxf(o11,0.f); o11 *= o11;
    } else {
      o00 += addsrc[(size_t)(2*p)*FWSZ + base];     o01 += addsrc[(size_t)(2*p)*FWSZ + base + 1];
      o10 += addsrc[(size_t)(2*p+1)*FWSZ + base];   o11 += addsrc[(size_t)(2*p+1)*FWSZ + base + 1];
    }
    o[(size_t)(2*p)*FWSZ   + base]     = o00;
    o[(size_t)(2*p)*FWSZ   + base + 1] = o01;
    o[(size_t)(2*p+1)*FWSZ + base]     = o10;
    o[(size_t)(2*p+1)*FWSZ + base + 1] = o11;
  }
}

extern "C" void kernel_launch(void* const* d_in, const int* in_sizes, int n_in,
                              void* d_out, int out_size){
  const float *x    = (const float*)d_in[0],  *skip = (const float*)d_in[1];
  const float *pqb1 = (const float*)d_in[2],  *pqb2 = (const float*)d_in[3], *sqk = (const float*)d_in[4];
  const float *g1 = (const float*)d_in[5],  *b1 = (const float*)d_in[6];
  const float *wq1 = (const float*)d_in[7], *wk1 = (const float*)d_in[8],
              *wv1 = (const float*)d_in[9], *wo1 = (const float*)d_in[10];
  const float *g2 = (const float*)d_in[11], *b2 = (const float*)d_in[12];
  const float *wq2 = (const float*)d_in[13], *wk2 = (const float*)d_in[14],
              *wv2 = (const float*)d_in[15], *wo2 = (const float*)d_in[16];
  const float *g3 = (const float*)d_in[17], *b3 = (const float*)d_in[18];
  const float *wc1 = (const float*)d_in[19], *wc2 = (const float*)d_in[20];

  float* out = (float*)d_out;
  float* pq1 = out + 8u*FWSZ;          // 4,194,304
  float* pq2 = pq1 + 64u*QKS;          // +16,777,216

  float* S = nullptr;
  cudaGetSymbolAddress((void**)&S, g_scratch);
  float* NX = S;
  float* Qp = S + (size_t)8u*FWSZ;
  float* Kp = S + (size_t)16u*FWSZ;
  float* Vp = S + (size_t)24u*FWSZ;
  float* Ap = S + (size_t)32u*FWSZ;
  float* Hp = S + (size_t)40u*FWSZ;    // 24 planes: x | z1 | z2
  float* NH = S + (size_t)64u*FWSZ;    // 24 planes
  float* Tp = S + (size_t)88u*FWSZ;    // 32 planes
  float* MX = S + (size_t)120u*FWSZ;
  float* IV = MX + 32768;

  // ---- attention 1 ----
  k_copy<<<4096, 256>>>(x, Hp);                              // H[0:8] = x
  k_ln<<<dim3(16,8), 256>>>(x, g1, b1, NX);
  k_conv1x3<8,4><<<1024, 256>>>(NX, wq1, Qp);
  k_conv1x3<8,4><<<1024, 256>>>(NX, wk1, Kp);
  k_conv1x3<8,4><<<1024, 256>>>(NX, wv1, Vp);
  k_gemm_qk<<<dim3(4,4,64), 256>>>(Qp, Kp, pqb1, sqk, nullptr, pq1);
  k_stats<<<32768, 128>>>(pq1, MX, IV);
  k_gemm_av<<<dim3(4,1,64), 256>>>(Vp, pq1, MX, IV, Ap);
  k_conv1x3<8,4><<<1024, 256>>>(Ap, wo1, Hp + (size_t)8u*FWSZ);   // z1

  // ---- attention 2 ----
  k_ln<<<dim3(16,16), 256>>>(Hp, g2, b2, NH);
  k_conv1x3<16,4><<<1024, 256>>>(NH, wq2, Qp);
  k_conv1x3<8,4><<<1024, 256>>>(skip, wk2, Kp);
  k_conv1x3<8,4><<<1024, 256>>>(skip, wv2, Vp);
  k_gemm_qk<<<dim3(4,4,64), 256>>>(Qp, Kp, sqk, pqb2, pq1, pq2);
  k_stats<<<32768, 128>>>(pq2, MX, IV);
  k_gemm_av<<<dim3(4,1,64), 256>>>(Vp, pq2, MX, IV, Ap);
  k_conv1x3<8,4><<<1024, 256>>>(Ap, wo2, Hp + (size_t)16u*FWSZ);  // z2

  // ---- conv MLP + residual ----
  k_ln<<<dim3(16,24), 256>>>(Hp, g3, b3, NH);
  k_conv3x3<24,16,true><<<1024, 256>>>(NH, wc1, nullptr, Tp);     // sqrelu
  k_conv3x3<32,4,false><<<1024, 256>>>(Tp, wc2, x, out);          // + x
}

// round 6
// speedup vs baseline: 1.0264x; 1.0264x over previous
#include <cuda_runtime.h>

#define FWSZ 524288u
#define QKS  262144u
typedef unsigned long long ull;

static __device__ __forceinline__ ull pack2(float lo, float hi){
  ull r; asm("mov.b64 %0,{%1,%2};" : "=l"(r) : "f"(lo), "f"(hi)); return r;
}
static __device__ __forceinline__ void fma2(ull &d, ull a, ull b){
  asm("fma.rn.f32x2 %0,%1,%2,%0;" : "+l"(d) : "l"(a), "l"(b));
}
static __device__ __forceinline__ float2 unpack2(ull v){
  float2 f; asm("mov.b64 {%0,%1},%2;" : "=f"(f.x), "=f"(f.y) : "l"(v)); return f;
}

// planes: Q 0..7, K 8..15, V 16..23, A 24..31, H 32..55, T 56..87; then musig + pmax + psum
__device__ float g_scratch[88u*FWSZ + 300000u];

// ---------------- float4 copy ----------------
__global__ void k_copy(const float* __restrict__ s, float* __restrict__ d){
  unsigned i = blockIdx.x*256u + threadIdx.x;
  ((float4*)d)[i] = ((const float4*)s)[i];
}

// ---------------- LN stats over F per (c,w): write {mu, rsqrt(var+eps)} ----------------
__global__ __launch_bounds__(256) void k_stats(const float* __restrict__ in, float2* __restrict__ ms){
  int c = blockIdx.y, lane = threadIdx.x & 31, fg = threadIdx.x >> 5;
  int w = blockIdx.x*32 + lane;
  const float* base = in + (size_t)c*FWSZ + w;
  float s = 0.f, s2 = 0.f;
  for (int f = fg; f < 1024; f += 8){ float v = base[(size_t)f*512u]; s += v; s2 += v*v; }
  __shared__ float sh[2][8][32];
  sh[0][fg][lane] = s; sh[1][fg][lane] = s2;
  __syncthreads();
  if (fg == 0){
    float S = 0.f, S2 = 0.f;
    #pragma unroll
    for (int r = 0; r < 8; r++){ S += sh[0][r][lane]; S2 += sh[1][r][lane]; }
    float mu  = S*(1.f/1024.f);
    float var = S2*(1.f/1024.f) - mu*mu;
    ms[c*512 + w] = make_float2(mu, rsqrtf(var + 1e-8f));
  }
}

// ---------------- fused (optional-LN) 1x3 conv, up to 3 output tensors of 8 ch each ----------------
// 2 px/thread, packed oc pairs (OCP=4 per output)
template<int IC, int NO, bool LN>
__global__ __launch_bounds__(256) void k_lnconv(const float* __restrict__ in, const float2* __restrict__ ms,
    const float* __restrict__ g, const float* __restrict__ b,
    const float* __restrict__ w0, const float* __restrict__ w1, const float* __restrict__ w2,
    float* __restrict__ o0, float* __restrict__ o1, float* __restrict__ o2)
{
  __shared__ ull ws[NO*4*IC*3];
  for (int i = threadIdx.x; i < NO*4*IC*3; i += 256){
    int s = i/(4*IC*3), r = i - s*(4*IC*3);
    const float* wsrc = (s==0)? w0 : (s==1)? w1 : w2;
    int p = r/(IC*3), rr = r - p*(IC*3);
    ws[i] = pack2(wsrc[(2*p)*IC*3 + rr], wsrc[(2*p+1)*IC*3 + rr]);
  }
  __syncthreads();
  unsigned t = blockIdx.x*256u + threadIdx.x;
  unsigned base = t*2u;
  int w = base & 511u, f = base >> 9;
  bool w0v = (w > 0), w3v = (w < 510);
  ull acc[NO*4][2];
  #pragma unroll
  for (int p = 0; p < NO*4; p++){ acc[p][0] = 0ull; acc[p][1] = 0ull; }
  #pragma unroll
  for (int ic = 0; ic < IC; ic++){
    const float* ip = in + (size_t)ic*FWSZ + base;
    float v0 = w0v ? ip[-1] : 0.f, v1 = ip[0], v2 = ip[1], v3 = w3v ? ip[2] : 0.f;
    float n0, n1, n2, n3;
    if (LN){
      float gf = g[ic*1024 + f], bf = b[ic*1024 + f];
      const float2* msc = ms + ic*512;
      if (w0v){ float2 m = msc[w-1]; float sc = m.y*gf; n0 = v0*sc + (bf - m.x*sc); } else n0 = 0.f;
      { float2 m = msc[w];   float sc = m.y*gf; n1 = v1*sc + (bf - m.x*sc); }
      { float2 m = msc[w+1]; float sc = m.y*gf; n2 = v2*sc + (bf - m.x*sc); }
      if (w3v){ float2 m = msc[w+2]; float sc = m.y*gf; n3 = v3*sc + (bf - m.x*sc); } else n3 = 0.f;
    } else { n0 = v0; n1 = v1; n2 = v2; n3 = v3; }
    ull b0 = pack2(n0,n0), b1 = pack2(n1,n1), b2 = pack2(n2,n2), b3 = pack2(n3,n3);
    #pragma unroll
    for (int p = 0; p < NO*4; p++){
      const ull* wp = &ws[(p*IC + ic)*3];
      ull q0 = wp[0], q1 = wp[1], q2 = wp[2];
      fma2(acc[p][0], b0, q0); fma2(acc[p][0], b1, q1); fma2(acc[p][0], b2, q2);
      fma2(acc[p][1], b1, q0); fma2(acc[p][1], b2, q1); fma2(acc[p][1], b3, q2);
    }
  }
  #pragma unroll
  for (int s = 0; s < NO; s++){
    float* ob = (s==0)? o0 : (s==1)? o1 : o2;
    #pragma unroll
    for (int p = 0; p < 4; p++){
      float2 a = unpack2(acc[s*4+p][0]), c = unpack2(acc[s*4+p][1]);
      ob[(size_t)(2*p)*FWSZ   + base]     = a.x;
      ob[(size_t)(2*p)*FWSZ   + base + 1] = c.x;
      ob[(size_t)(2*p+1)*FWSZ + base]     = a.y;
      ob[(size_t)(2*p+1)*FWSZ + base + 1] = c.y;
    }
  }
}

// ---------------- QK^T GEMM + bias epilogue + fused partial softmax stats ----------------
__global__ __launch_bounds__(256) void k_gemm_qk(const float* __restrict__ Q, const float* __restrict__ K,
    const float* __restrict__ b1p, const float* __restrict__ b2p, const float* __restrict__ b3p,
    float* __restrict__ o, float* __restrict__ pmax, float* __restrict__ psum){
  int z = blockIdx.z, qw0 = blockIdx.y*128, kw0 = blockIdx.x*128, bx = blockIdx.x;
  const float* Qb = Q + (size_t)z*65536u + qw0;
  const float* Kb = K + (size_t)z*65536u + kw0;
  __shared__ __align__(16) float As[16][128], Bs[16][128];
  int tid = threadIdx.x, tx = tid & 15, ty = tid >> 4;
  ull acc[8][4];
  #pragma unroll
  for (int i = 0; i < 8; i++)
    #pragma unroll
    for (int j = 0; j < 4; j++) acc[i][j] = 0ull;
  for (int d0 = 0; d0 < 128; d0 += 16){
    #pragma unroll
    for (int r = 0; r < 2; r++){
      int idx = tid + 256*r;
      int kk = idx >> 5, m4 = (idx & 31)*4;
      *(float4*)&As[kk][m4] = *(const float4*)&Qb[(size_t)(d0+kk)*512u + m4];
      *(float4*)&Bs[kk][m4] = *(const float4*)&Kb[(size_t)(d0+kk)*512u + m4];
    }
    __syncthreads();
    #pragma unroll
    for (int kk = 0; kk < 16; kk++){
      float4 a0 = *(float4*)&As[kk][ty*8], a1 = *(float4*)&As[kk][ty*8+4];
      float4 p0 = *(float4*)&Bs[kk][tx*8], p1 = *(float4*)&Bs[kk][tx*8+4];
      ull pb0 = pack2(p0.x,p0.y), pb1 = pack2(p0.z,p0.w), pb2 = pack2(p1.x,p1.y), pb3 = pack2(p1.z,p1.w);
      float aa[8] = {a0.x,a0.y,a0.z,a0.w,a1.x,a1.y,a1.z,a1.w};
      #pragma unroll
      for (int i = 0; i < 8; i++){
        ull ab = pack2(aa[i], aa[i]);
        fma2(acc[i][0], ab, pb0); fma2(acc[i][1], ab, pb1);
        fma2(acc[i][2], ab, pb2); fma2(acc[i][3], ab, pb3);
      }
    }
    __syncthreads();
  }
  const float sc = 0.08838834764831845f;  // 1/sqrt(128)
  #pragma unroll
  for (int i = 0; i < 8; i++){
    int row = qw0 + ty*8 + i;
    size_t rb = (size_t)z*QKS + (size_t)row*512u + kw0 + tx*8;
    float ov[8];
    #pragma unroll
    for (int j = 0; j < 4; j++){
      float2 v = unpack2(acc[i][j]);
      size_t ix = rb + j*2;
      float2 c1 = *(const float2*)(b1p + ix), c2 = *(const float2*)(b2p + ix);
      float o0 = v.x*sc + c1.x + c2.x, o1 = v.y*sc + c1.y + c2.y;
      if (b3p){ float2 c3 = *(const float2*)(b3p + ix); o0 += c3.x; o1 += c3.y; }
      *(float2*)(o + ix) = make_float2(o0, o1);
      ov[2*j] = o0; ov[2*j+1] = o1;
    }
    float m = ov[0];
    #pragma unroll
    for (int k2 = 1; k2 < 8; k2++) m = fmaxf(m, ov[k2]);
    #pragma unroll
    for (int off = 8; off; off >>= 1) m = fmaxf(m, __shfl_xor_sync(0xffffffffu, m, off));
    float s = 0.f;
    #pragma unroll
    for (int k2 = 0; k2 < 8; k2++) s += __expf(ov[k2] - m);
    #pragma unroll
    for (int off = 8; off; off >>= 1) s += __shfl_xor_sync(0xffffffffu, s, off);
    if (tx == 0){
      size_t pi = ((size_t)z*512u + row)*4u + bx;
      pmax[pi] = m; psum[pi] = s;
    }
  }
}

// ---------------- AV GEMM, softmax fused (stats combined in prologue) ----------------
__global__ __launch_bounds__(256) void k_gemm_av(const float* __restrict__ V, const float* __restrict__ pq,
    const float* __restrict__ pmax, const float* __restrict__ psum, float* __restrict__ A){
  int z = blockIdx.z, qw0 = blockIdx.x*128;
  const float* Vb = V  + (size_t)z*65536u;
  const float* Pb = pq + (size_t)z*QKS;
  __shared__ float mxs[128], ivs[128];
  __shared__ __align__(16) float As[16][132], Bs[16][132];
  int tid = threadIdx.x, tx = tid & 15, ty = tid >> 4;
  if (tid < 128){
    size_t pi = ((size_t)z*512u + qw0 + tid)*4u;
    float m0 = pmax[pi], m1 = pmax[pi+1], m2 = pmax[pi+2], m3 = pmax[pi+3];
    float m = fmaxf(fmaxf(m0,m1), fmaxf(m2,m3));
    float s = psum[pi]*__expf(m0-m) + psum[pi+1]*__expf(m1-m)
            + psum[pi+2]*__expf(m2-m) + psum[pi+3]*__expf(m3-m);
    mxs[tid] = m; ivs[tid] = 1.f/s;
  }
  __syncthreads();
  ull acc[8][4];
  #pragma unroll
  for (int i = 0; i < 8; i++)
    #pragma unroll
    for (int j = 0; j < 4; j++) acc[i][j] = 0ull;
  for (int kw0 = 0; kw0 < 512; kw0 += 16){
    #pragma unroll
    for (int r = 0; r < 8; r++){
      int idx = tid + 256*r;
      int m = idx >> 4, kk = idx & 15;
      As[kk][m] = Vb[(size_t)m*512u + kw0 + kk];
      Bs[kk][m] = __expf(Pb[(size_t)(qw0 + m)*512u + kw0 + kk] - mxs[m]);
    }
    __syncthreads();
    #pragma unroll
    for (int kk = 0; kk < 16; kk++){
      float4 a0 = *(float4*)&As[kk][ty*8], a1 = *(float4*)&As[kk][ty*8+4];
      float4 p0 = *(float4*)&Bs[kk][tx*8], p1 = *(float4*)&Bs[kk][tx*8+4];
      ull pb0 = pack2(p0.x,p0.y), pb1 = pack2(p0.z,p0.w), pb2 = pack2(p1.x,p1.y), pb3 = pack2(p1.z,p1.w);
      float aa[8] = {a0.x,a0.y,a0.z,a0.w,a1.x,a1.y,a1.z,a1.w};
      #pragma unroll
      for (int i = 0; i < 8; i++){
        ull ab = pack2(aa[i], aa[i]);
        fma2(acc[i][0], ab, pb0); fma2(acc[i][1], ab, pb1);
        fma2(acc[i][2], ab, pb2); fma2(acc[i][3], ab, pb3);
      }
    }
    __syncthreads();
  }
  #pragma unroll
  for (int i = 0; i < 8; i++){
    size_t rb = ((size_t)z*128u + ty*8 + i)*512u + qw0 + tx*8;
    #pragma unroll
    for (int j = 0; j < 4; j++){
      float2 v  = unpack2(acc[i][j]);
      float2 iv = *(float2*)&ivs[tx*8 + j*2];
      *(float2*)(A + rb + j*2) = make_float2(v.x*iv.x, v.y*iv.y);
    }
  }
}

// ---------------- 3x3 conv with fused LN on input (24ch -> 32ch), SquaredReLU ----------------
__global__ __launch_bounds__(256) void k_c3ln(const float* __restrict__ in, const float2* __restrict__ ms,
    const float* __restrict__ g, const float* __restrict__ b, const float* __restrict__ wgt,
    float* __restrict__ o)
{
  __shared__ ull ws[16*24*9];
  for (int i = threadIdx.x; i < 16*24*9; i += 256){
    int p = i/216, r = i - p*216;
    ws[i] = pack2(wgt[(2*p)*216 + r], wgt[(2*p+1)*216 + r]);
  }
  __syncthreads();
  unsigned t = blockIdx.x*256u + threadIdx.x;
  unsigned base = t*2u;
  int w = base & 511u, f = base >> 9;
  bool r0v = (f > 0), r2v = (f < 1023), w0v = (w > 0), w3v = (w < 510);
  ull acc[16][2];
  #pragma unroll
  for (int p = 0; p < 16; p++){ acc[p][0] = 0ull; acc[p][1] = 0ull; }
  #pragma unroll 2
  for (int ic = 0; ic < 24; ic++){
    const float* ip = in + (size_t)ic*FWSZ + base;
    const float2* msc = ms + ic*512;
    float gm1 = r0v ? g[ic*1024+f-1] : 0.f, bm1 = r0v ? b[ic*1024+f-1] : 0.f;
    float gc  = g[ic*1024+f],               bc  = b[ic*1024+f];
    float gp1 = r2v ? g[ic*1024+f+1] : 0.f, bp1 = r2v ? b[ic*1024+f+1] : 0.f;
    float2 m0 = w0v ? msc[w-1] : make_float2(0.f,1.f);
    float2 m1 = msc[w], m2 = msc[w+1];
    float2 m3 = w3v ? msc[w+2] : make_float2(0.f,1.f);
    float u[3][4];
    {
      const float* rp = ip - 512;
      u[0][0] = (r0v&&w0v)? rp[-1]:0.f; u[0][1] = r0v? rp[0]:0.f; u[0][2] = r0v? rp[1]:0.f; u[0][3] = (r0v&&w3v)? rp[2]:0.f;
      u[1][0] = w0v? ip[-1]:0.f;        u[1][1] = ip[0];          u[1][2] = ip[1];          u[1][3] = w3v? ip[2]:0.f;
      const float* rq = ip + 512;
      u[2][0] = (r2v&&w0v)? rq[-1]:0.f; u[2][1] = r2v? rq[0]:0.f; u[2][2] = r2v? rq[1]:0.f; u[2][3] = (r2v&&w3v)? rq[2]:0.f;
    }
    auto nrm = [] (float v, float2 m, float gg, float bb, bool valid)->float{
      float sc = m.y*gg; return valid ? (v*sc + (bb - m.x*sc)) : 0.f; };
    u[0][0] = nrm(u[0][0], m0, gm1, bm1, r0v&&w0v);
    u[0][1] = nrm(u[0][1], m1, gm1, bm1, r0v);
    u[0][2] = nrm(u[0][2], m2, gm1, bm1, r0v);
    u[0][3] = nrm(u[0][3], m3, gm1, bm1, r0v&&w3v);
    u[1][0] = nrm(u[1][0], m0, gc,  bc,  w0v);
    u[1][1] = nrm(u[1][1], m1, gc,  bc,  true);
    u[1][2] = nrm(u[1][2], m2, gc,  bc,  true);
    u[1][3] = nrm(u[1][3], m3, gc,  bc,  w3v);
    u[2][0] = nrm(u[2][0], m0, gp1, bp1, r2v&&w0v);
    u[2][1] = nrm(u[2][1], m1, gp1, bp1, r2v);
    u[2][2] = nrm(u[2][2], m2, gp1, bp1, r2v);
    u[2][3] = nrm(u[2][3], m3, gp1, bp1, r2v&&w3v);
    #pragma unroll
    for (int k = 0; k < 9; k++){
      int ky = k/3, kx = k - ky*3;
      ull b0 = pack2(u[ky][kx],   u[ky][kx]);
      ull b1 = pack2(u[ky][kx+1], u[ky][kx+1]);
      #pragma unroll
      for (int p = 0; p < 16; p++){
        ull wv = ws[(p*24 + ic)*9 + k];
        fma2(acc[p][0], b0, wv); fma2(acc[p][1], b1, wv);
      }
    }
  }
  #pragma unroll
  for (int p = 0; p < 16; p++){
    float2 a = unpack2(acc[p][0]), bv = unpack2(acc[p][1]);
    float o00 = fmaxf(a.x, 0.f);  o00 *= o00;
    float o10 = fmaxf(a.y, 0.f);  o10 *= o10;
    float o01 = fmaxf(bv.x, 0.f); o01 *= o01;
    float o11 = fmaxf(bv.y, 0.f); o11 *= o11;
    o[(size_t)(2*p)*FWSZ   + base]     = o00;
    o[(size_t)(2*p)*FWSZ   + base + 1] = o01;
    o[(size_t)(2*p+1)*FWSZ + base]     = o10;
    o[(size_t)(2*p+1)*FWSZ + base + 1] = o11;
  }
}

// ---------------- plain 3x3 conv (32ch -> 8ch) + residual add ----------------
__global__ __launch_bounds__(256) void k_c3b(const float* __restrict__ in, const float* __restrict__ wgt,
    const float* __restrict__ addsrc, float* __restrict__ o)
{
  __shared__ ull ws[4*32*9];
  for (int i = threadIdx.x; i < 4*32*9; i += 256){
    int p = i/288, r = i - p*288;
    ws[i] = pack2(wgt[(2*p)*288 + r], wgt[(2*p+1)*288 + r]);
  }
  __syncthreads();
  unsigned t = blockIdx.x*256u + threadIdx.x;
  unsigned base = t*2u;
  int w = base & 511u, f = base >> 9;
  bool r0v = (f > 0), r2v = (f < 1023), w0v = (w > 0), w3v = (w < 510);
  ull acc[4][2];
  #pragma unroll
  for (int p = 0; p < 4; p++){ acc[p][0] = 0ull; acc[p][1] = 0ull; }
  #pragma unroll 4
  for (int ic = 0; ic < 32; ic++){
    const float* ip = in + (size_t)ic*FWSZ + base;
    float u[3][4];
    {
      const float* rp = ip - 512;
      u[0][0] = (r0v&&w0v)? rp[-1]:0.f; u[0][1] = r0v? rp[0]:0.f; u[0][2] = r0v? rp[1]:0.f; u[0][3] = (r0v&&w3v)? rp[2]:0.f;
      u[1][0] = w0v? ip[-1]:0.f;        u[1][1] = ip[0];          u[1][2] = ip[1];          u[1][3] = w3v? ip[2]:0.f;
      const float* rq = ip + 512;
      u[2][0] = (r2v&&w0v)? rq[-1]:0.f; u[2][1] = r2v? rq[0]:0.f; u[2][2] = r2v? rq[1]:0.f; u[2][3] = (r2v&&w3v)? rq[2]:0.f;
    }
    #pragma unroll
    for (int k = 0; k < 9; k++){
      int ky = k/3, kx = k - ky*3;
      ull b0 = pack2(u[ky][kx],   u[ky][kx]);
      ull b1 = pack2(u[ky][kx+1], u[ky][kx+1]);
      #pragma unroll
      for (int p = 0; p < 4; p++){
        ull wv = ws[(p*32 + ic)*9 + k];
        fma2(acc[p][0], b0, wv); fma2(acc[p][1], b1, wv);
      }
    }
  }
  #pragma unroll
  for (int p = 0; p < 4; p++){
    float2 a = unpack2(acc[p][0]), bv = unpack2(acc[p][1]);
    float o00 = a.x + addsrc[(size_t)(2*p)*FWSZ + base];
    float o01 = bv.x + addsrc[(size_t)(2*p)*FWSZ + base + 1];
    float o10 = a.y + addsrc[(size_t)(2*p+1)*FWSZ + base];
    float o11 = bv.y + addsrc[(size_t)(2*p+1)*FWSZ + base + 1];
    o[(size_t)(2*p)*FWSZ   + base]     = o00;
    o[(size_t)(2*p)*FWSZ   + base + 1] = o01;
    o[(size_t)(2*p+1)*FWSZ + base]     = o10;
    o[(size_t)(2*p+1)*FWSZ + base + 1] = o11;
  }
}

extern "C" void kernel_launch(void* const* d_in, const int* in_sizes, int n_in,
                              void* d_out, int out_size){
  const float *x    = (const float*)d_in[0],  *skip = (const float*)d_in[1];
  const float *pqb1 = (const float*)d_in[2],  *pqb2 = (const float*)d_in[3], *sqk = (const float*)d_in[4];
  const float *g1 = (const float*)d_in[5],  *b1 = (const float*)d_in[6];
  const float *wq1 = (const float*)d_in[7], *wk1 = (const float*)d_in[8],
              *wv1 = (const float*)d_in[9], *wo1 = (const float*)d_in[10];
  const float *g2 = (const float*)d_in[11], *b2 = (const float*)d_in[12];
  const float *wq2 = (const float*)d_in[13], *wk2 = (const float*)d_in[14],
              *wv2 = (const float*)d_in[15], *wo2 = (const float*)d_in[16];
  const float *g3 = (const float*)d_in[17], *b3 = (const float*)d_in[18];
  const float *wc1 = (const float*)d_in[19], *wc2 = (const float*)d_in[20];

  float* out = (float*)d_out;
  float* pq1 = out + 8u*FWSZ;
  float* pq2 = pq1 + 64u*QKS;

  float* S = nullptr;
  cudaGetSymbolAddress((void**)&S, g_scratch);
  float*  Qp = S;
  float*  Kp = S + (size_t)8u*FWSZ;
  float*  Vp = S + (size_t)16u*FWSZ;
  float*  Ap = S + (size_t)24u*FWSZ;
  float*  Hp = S + (size_t)32u*FWSZ;   // 24 planes: x | z1 | z2
  float*  Tp = S + (size_t)56u*FWSZ;   // 32 planes
  float2* MS = (float2*)(S + (size_t)88u*FWSZ);
  float*  PM = S + (size_t)88u*FWSZ + 24576u;
  float*  PS = PM + 131072u;

  // ---- attention 1 ----
  k_copy<<<4096, 256>>>(x, Hp);
  k_stats<<<dim3(16,8), 256>>>(Hp, MS);
  k_lnconv<8,3,true><<<1024, 256>>>(Hp, MS, g1, b1, wq1, wk1, wv1, Qp, Kp, Vp);
  k_gemm_qk<<<dim3(4,4,64), 256>>>(Qp, Kp, pqb1, sqk, nullptr, pq1, PM, PS);
  k_gemm_av<<<dim3(4,1,64), 256>>>(Vp, pq1, PM, PS, Ap);
  k_lnconv<8,1,false><<<1024, 256>>>(Ap, nullptr, nullptr, nullptr, wo1, nullptr, nullptr,
                                     Hp + (size_t)8u*FWSZ, nullptr, nullptr);
  // ---- attention 2 ----
  k_stats<<<dim3(16,16), 256>>>(Hp, MS);
  k_lnconv<16,1,true><<<1024, 256>>>(Hp, MS, g2, b2, wq2, nullptr, nullptr, Qp, nullptr, nullptr);
  k_lnconv<8,2,false><<<1024, 256>>>(skip, nullptr, nullptr, nullptr, wk2, wv2, nullptr, Kp, Vp, nullptr);
  k_gemm_qk<<<dim3(4,4,64), 256>>>(Qp, Kp, sqk, pqb2, pq1, pq2, PM, PS);
  k_gemm_av<<<dim3(4,1,64), 256>>>(Vp, pq2, PM, PS, Ap);
  k_lnconv<8,1,false><<<1024, 256>>>(Ap, nullptr, nullptr, nullptr, wo2, nullptr, nullptr,
                                     Hp + (size_t)16u*FWSZ, nullptr, nullptr);
  // ---- conv MLP + residual ----
  k_stats<<<dim3(16,24), 256>>>(Hp, MS);
  k_c3ln<<<1024, 256>>>(Hp, MS, g3, b3, wc1, Tp);
  k_c3b<<<1024, 256>>>(Tp, wc2, x, out);
}